// round 15
// baseline (speedup 1.0000x reference)
#include <cuda_runtime.h>
#include <cuda_fp16.h>
#include <cstdint>
#include <cstddef>

// ============================================================================
// ComplexMixture via mma.sync fp16 (same 11-bit significand as tf32).
// Warp-specialized Gram: 10 MMA warps + 4 loader warps, 4-stage smem ring
// with named-barrier full/empty pairs. Fused single-kernel epilogue.
// ============================================================================

namespace {
constexpr int kB = 32;
constexpr int kS = 8192;
constexpr int kD = 64;
constexpr int kM = 128;                   // 2*D
constexpr int kSplit = 8;
constexpr int kBK = 32;                   // K rows per stage
constexpr int kKper = kS / kSplit;        // 1024
constexpr int kIters = kKper / kBK;       // 32
constexpr int kRowB = 272;                // bytes/row: 256 data + 16 pad
constexpr int kStageB = kBK * kRowB;      // 8704
constexpr int kNS = 4;                    // ring stages
constexpr int kThreads = 448;             // 10 MMA warps + 4 loader warps
}  // namespace

// Partial Gram scratch: [B][SPLIT][128][128] f32 (upper tiles valid)
__device__ float g_scratch[(size_t)kB * kSplit * kM * kM];

__device__ __forceinline__ uint32_t smem_u32(const void* p) {
    uint32_t a;
    asm("{ .reg .u64 t; cvta.to.shared.u64 t, %1; cvt.u32.u64 %0, t; }"
        : "=r"(a) : "l"(p));
    return a;
}
__device__ __forceinline__ void ldsm_x4_t(uint32_t addr, uint32_t* r) {
    asm volatile(
        "ldmatrix.sync.aligned.m8n8.x4.trans.shared.b16 {%0,%1,%2,%3}, [%4];"
        : "=r"(r[0]), "=r"(r[1]), "=r"(r[2]), "=r"(r[3]) : "r"(addr));
}
__device__ __forceinline__ void mma_f16(float* d, const uint32_t* a,
                                        const uint32_t* b0, const uint32_t* b1) {
    asm volatile(
        "mma.sync.aligned.m16n8k16.row.col.f32.f16.f16.f32 "
        "{%0,%1,%2,%3}, {%4,%5,%6,%7}, {%8,%9}, {%0,%1,%2,%3};"
        : "+f"(d[0]), "+f"(d[1]), "+f"(d[2]), "+f"(d[3])
        : "r"(a[0]), "r"(a[1]), "r"(a[2]), "r"(a[3]), "r"(*b0), "r"(*b1));
}
__device__ __forceinline__ void sts_f4h(uint32_t addr, float4 v) {
    __half2 lo = __floats2half2_rn(v.x, v.y);
    __half2 hi = __floats2half2_rn(v.z, v.w);
    asm volatile("st.shared.v2.b32 [%0], {%1, %2};"
                 :: "r"(addr),
                    "r"(*reinterpret_cast<uint32_t*>(&lo)),
                    "r"(*reinterpret_cast<uint32_t*>(&hi)) : "memory");
}
__device__ __forceinline__ void bar_sync(int id) {
    asm volatile("bar.sync %0, %1;" :: "r"(id), "r"(kThreads) : "memory");
}
__device__ __forceinline__ void bar_arrive(int id) {
    asm volatile("bar.arrive %0, %1;" :: "r"(id), "r"(kThreads) : "memory");
}

// ---------------------------------------------------------------------------
// Kernel 1: warp-specialized partial Gram.
// Warps 0..9: MMA (upper 32x32 tile each). Warps 10..13: loaders.
// Named barriers: full[s] = 1+s, empty[s] = 5+s (s in 0..3).
// ---------------------------------------------------------------------------
__global__ void __launch_bounds__(kThreads, 2)
gram_kernel(const float* __restrict__ xr, const float* __restrict__ xi) {
    __shared__ __align__(16) char xt[kNS * kStageB];  // 34816 B

    const int t = threadIdx.x;
    const int wid = t >> 5;
    const int lane = t & 31;
    const int b = blockIdx.x >> 3;
    const int p = blockIdx.x & 7;
    const uint32_t smem0 = smem_u32(xt);

    if (wid >= 10) {
        // ---------------- loader warps (4): rows lw*8 .. lw*8+7 per stage ---
        const int lw = wid - 10;
        const int half_sel = lane >> 4;  // 0: xr, 1: xi
        const int li = lane & 15;        // float4 index within tensor row
        const float* src = half_sel ? xi : xr;
        const float* gptr = src +
            ((size_t)b * kS + (size_t)p * kKper + (size_t)(lw * 8)) * kD +
            (size_t)(4 * li);
        const uint32_t sts0 =
            (uint32_t)(lw * 8 * kRowB + half_sel * 128 + li * 8);

        float4 cur[8];
#pragma unroll
        for (int j = 0; j < 8; ++j)
            cur[j] = *reinterpret_cast<const float4*>(gptr + (size_t)j * kD);

        for (int it = 0; it < kIters; ++it) {
            if (it >= kNS) bar_sync(5 + (it & 3));
            const uint32_t dst = smem0 + (uint32_t)((it & 3) * kStageB) + sts0;
#pragma unroll
            for (int j = 0; j < 8; ++j)
                sts_f4h(dst + (uint32_t)(j * kRowB), cur[j]);
            asm volatile("membar.cta;" ::: "memory");
            bar_arrive(1 + (it & 3));
            if (it + 1 < kIters) {
                const float* gn = gptr + (size_t)((it + 1) * kBK) * kD;
#pragma unroll
                for (int j = 0; j < 8; ++j)
                    cur[j] = *reinterpret_cast<const float4*>(gn + (size_t)j * kD);
            }
        }
        return;
    }

    // ---------------- MMA warps (10): upper 32x32 tile (ti, tj) ------------
    const int ti_tab[10] = {0, 0, 0, 0, 1, 1, 1, 2, 2, 3};
    const int tj_tab[10] = {0, 1, 2, 3, 1, 2, 3, 2, 3, 3};
    const int ti = ti_tab[wid];
    const int tj = tj_tab[wid];

    float acc[2][4][4];
#pragma unroll
    for (int mt = 0; mt < 2; ++mt)
#pragma unroll
        for (int nt = 0; nt < 4; ++nt)
#pragma unroll
            for (int e = 0; e < 4; ++e) acc[mt][nt][e] = 0.0f;

    // ldmatrix.x4.trans lane offsets (bytes within a stage buffer).
    const int g = lane >> 3;
    const int lr = lane & 7;
    uint32_t aoff[2], boff[2];
#pragma unroll
    for (int mt = 0; mt < 2; ++mt) {
        const int r0 = ti * 32 + mt * 16;
        aoff[mt] = (uint32_t)((lr + ((g >= 2) ? 8 : 0)) * kRowB + r0 * 2 +
                              ((g & 1) ? 16 : 0));
    }
#pragma unroll
    for (int np = 0; np < 2; ++np) {
        const int c0 = tj * 32 + np * 16;
        boff[np] = (uint32_t)((lr + ((g & 1) ? 8 : 0)) * kRowB + c0 * 2 +
                              ((g >= 2) ? 16 : 0));
    }

    for (int it = 0; it < kIters; ++it) {
        bar_sync(1 + (it & 3));
        const uint32_t sb = smem0 + (uint32_t)((it & 3) * kStageB);
#pragma unroll
        for (int ks = 0; ks < 2; ++ks) {
            const uint32_t ko = (uint32_t)(ks * 16 * kRowB);
            uint32_t A0[4], A1[4], B0[4], B1[4];
            ldsm_x4_t(sb + ko + aoff[0], A0);
            ldsm_x4_t(sb + ko + aoff[1], A1);
            ldsm_x4_t(sb + ko + boff[0], B0);
            ldsm_x4_t(sb + ko + boff[1], B1);
            mma_f16(acc[0][0], A0, B0 + 0, B0 + 1);
            mma_f16(acc[0][1], A0, B0 + 2, B0 + 3);
            mma_f16(acc[0][2], A0, B1 + 0, B1 + 1);
            mma_f16(acc[0][3], A0, B1 + 2, B1 + 3);
            mma_f16(acc[1][0], A1, B0 + 0, B0 + 1);
            mma_f16(acc[1][1], A1, B0 + 2, B0 + 3);
            mma_f16(acc[1][2], A1, B1 + 0, B1 + 1);
            mma_f16(acc[1][3], A1, B1 + 2, B1 + 3);
        }
        bar_arrive(5 + (it & 3));
    }

    // Epilogue: write this warp's 32x32 tile to scratch (float2 stores).
    const int fr = lane >> 2;
    const int fc = lane & 3;
    float* scr = g_scratch + (size_t)(b * kSplit + p) * kM * kM;
#pragma unroll
    for (int mt = 0; mt < 2; ++mt) {
#pragma unroll
        for (int nt = 0; nt < 4; ++nt) {
            const int row = ti * 32 + mt * 16 + fr;
            const int col = tj * 32 + nt * 8 + 2 * fc;
            float2 v0 = make_float2(acc[mt][nt][0], acc[mt][nt][1]);
            float2 v1 = make_float2(acc[mt][nt][2], acc[mt][nt][3]);
            *reinterpret_cast<float2*>(scr + (size_t)row * kM + col) = v0;
            *reinterpret_cast<float2*>(scr + (size_t)(row + 8) * kM + col) = v1;
        }
    }
}

// ---------------------------------------------------------------------------
// Kernel 2: fused epilogue. grid = 64: (batch, role). role 0 = real (needs
// tiles of blocks 00 and 11), role 1 = imag (block 01). Tiles are summed
// over the 8 splits into padded smem, outputs computed with smem transposes
// (conflict-free, pitch 33) and fully coalesced GMEM writes.
// ---------------------------------------------------------------------------
__global__ void __launch_bounds__(512)
epilogue_kernel(float* __restrict__ out) {
    __shared__ float tl[6][32][33];

    const int b = blockIdx.x >> 1;
    const int role = blockIdx.x & 1;
    const int t = threadIdx.x;
    const float invS = 1.0f / (float)kS;

    // Tile lists (all within the computed upper set ti<=tj).
    // real: (0,0),(0,1),(1,1),(2,2),(2,3),(3,3)   imag: (0,2),(0,3),(1,2),(1,3)
    const int ti_r[6] = {0, 0, 1, 2, 2, 3};
    const int tj_r[6] = {0, 1, 1, 2, 3, 3};
    const int ti_i[4] = {0, 0, 1, 1};
    const int tj_i[4] = {2, 3, 2, 3};
    const int ntiles = role ? 4 : 6;

    const float* base = g_scratch + (size_t)b * kSplit * kM * kM;
    for (int idx = t; idx < ntiles * 256; idx += 512) {
        const int slot = idx >> 8;
        const int e = idx & 255;
        const int r = e >> 3;
        const int c4 = (e & 7) * 4;
        const int ti = role ? ti_i[slot] : ti_r[slot];
        const int tj = role ? tj_i[slot] : tj_r[slot];
        const float* src =
            base + (size_t)(ti * 32 + r) * kM + (size_t)(tj * 32 + c4);
        float4 s = make_float4(0.f, 0.f, 0.f, 0.f);
#pragma unroll
        for (int pp = 0; pp < kSplit; ++pp) {
            const float4 v =
                *reinterpret_cast<const float4*>(src + (size_t)pp * kM * kM);
            s.x += v.x; s.y += v.y; s.z += v.z; s.w += v.w;
        }
        tl[slot][r][c4 + 0] = s.x;
        tl[slot][r][c4 + 1] = s.y;
        tl[slot][r][c4 + 2] = s.z;
        tl[slot][r][c4 + 3] = s.w;
    }
    __syncthreads();

    if (role == 0) {
        // out_real[i][j] = (G00(i,j) + G11(i,j)) / S; blocks symmetric.
        float* dst = out + (size_t)b * kD * kD;
        for (int idx = t; idx < kD * kD; idx += 512) {
            const int i = idx >> 6;
            const int j = idx & 63;
            const int ii = (i <= j) ? i : j;
            const int jj = (i <= j) ? j : i;
            const int s00 = (ii >> 5) + (jj >> 5);       // 0,1,2
            const float g00 = tl[s00][ii & 31][jj & 31];
            const float g11 = tl[3 + s00][ii & 31][jj & 31];
            dst[idx] = (g00 + g11) * invS;
        }
    } else {
        // out_imag[i][j] = (G01[i][j] - G01[j][i]) / S
        float* dst = out + (size_t)kB * kD * kD + (size_t)b * kD * kD;
        for (int idx = t; idx < kD * kD; idx += 512) {
            const int i = idx >> 6;
            const int j = idx & 63;
            const float a = tl[(i >> 5) * 2 + (j >> 5)][i & 31][j & 31];
            const float c = tl[(j >> 5) * 2 + (i >> 5)][j & 31][i & 31];
            dst[idx] = (a - c) * invS;
        }
    }
}

// ---------------------------------------------------------------------------
extern "C" void kernel_launch(void* const* d_in, const int* in_sizes, int n_in,
                              void* d_out, int out_size) {
    const float* xr = (const float*)d_in[0];
    const float* xi = (const float*)d_in[1];
    float* out = (float*)d_out;

    gram_kernel<<<kB * kSplit, kThreads>>>(xr, xi);
    epilogue_kernel<<<kB * 2, 512>>>(out);
}

// round 16
// speedup vs baseline: 1.1024x; 1.1024x over previous
#include <cuda_runtime.h>
#include <cuda_fp16.h>
#include <cstdint>
#include <cstddef>

// ============================================================================
// ComplexMixture via mma.sync fp16 (same 11-bit significand as tf32).
// G = X^T X per batch, X = [R | I] (S x 128); symmetric -> 10 upper 32x32
// warp tiles. K split across 9 CTAs/batch (grid 288 ~= 296 CTA slots),
// uneven deterministic partition (4x29 + 5x28 iters of BK=32).
// Fused epilogue: grid 128 = batch x {real-lo, real-hi, imag-lo, imag-hi}.
// ============================================================================

namespace {
constexpr int kB = 32;
constexpr int kS = 8192;
constexpr int kD = 64;
constexpr int kM = 128;                   // 2*D
constexpr int kSplit = 9;
constexpr int kBK = 32;                   // K rows per stage
constexpr int kRowB = 272;                // bytes/row: 256 data + 16 pad
constexpr int kStageB = kBK * kRowB;      // 8704
}  // namespace

// Partial Gram scratch: [B][SPLIT][128][128] f32 (upper tiles valid)
__device__ float g_scratch[(size_t)kB * kSplit * kM * kM];

__device__ __forceinline__ uint32_t smem_u32(const void* p) {
    uint32_t a;
    asm("{ .reg .u64 t; cvta.to.shared.u64 t, %1; cvt.u32.u64 %0, t; }"
        : "=r"(a) : "l"(p));
    return a;
}
__device__ __forceinline__ void ldsm_x4_t(uint32_t addr, uint32_t* r) {
    asm volatile(
        "ldmatrix.sync.aligned.m8n8.x4.trans.shared.b16 {%0,%1,%2,%3}, [%4];"
        : "=r"(r[0]), "=r"(r[1]), "=r"(r[2]), "=r"(r[3]) : "r"(addr));
}
__device__ __forceinline__ void mma_f16(float* d, const uint32_t* a,
                                        const uint32_t* b0, const uint32_t* b1) {
    asm volatile(
        "mma.sync.aligned.m16n8k16.row.col.f32.f16.f16.f32 "
        "{%0,%1,%2,%3}, {%4,%5,%6,%7}, {%8,%9}, {%0,%1,%2,%3};"
        : "+f"(d[0]), "+f"(d[1]), "+f"(d[2]), "+f"(d[3])
        : "r"(a[0]), "r"(a[1]), "r"(a[2]), "r"(a[3]), "r"(*b0), "r"(*b1));
}
__device__ __forceinline__ void sts_f4h(uint32_t addr, float4 v) {
    __half2 lo = __floats2half2_rn(v.x, v.y);
    __half2 hi = __floats2half2_rn(v.z, v.w);
    asm volatile("st.shared.v2.b32 [%0], {%1, %2};"
                 :: "r"(addr),
                    "r"(*reinterpret_cast<uint32_t*>(&lo)),
                    "r"(*reinterpret_cast<uint32_t*>(&hi)) : "memory");
}

// ---------------------------------------------------------------------------
// Kernel 1: per-(batch, split) partial Gram via mma.sync fp16 + ldmatrix.trans
// 320 threads = 10 warps; warp w owns upper 32x32 tile (ti, tj).
// Warps 0..7 are loaders (4 smem rows each per stage). 2 CTAs/SM.
// ---------------------------------------------------------------------------
__global__ void __launch_bounds__(320, 2)
gram_kernel(const float* __restrict__ xr, const float* __restrict__ xi) {
    __shared__ __align__(16) char xt[2 * kStageB];  // 17408 B

    const int t = threadIdx.x;
    const int wid = t >> 5;
    const int lane = t & 31;
    const int b = blockIdx.x / kSplit;
    const int p = blockIdx.x - b * kSplit;

    // Deterministic uneven K partition: splits 0..3 get 29 iters, 4..8 get 28.
    const int it0 = p * 28 + (p < 4 ? p : 4);     // prefix in BK units
    const int niter = 28 + (p < 4 ? 1 : 0);

    const int ti_tab[10] = {0, 0, 0, 0, 1, 1, 1, 2, 2, 3};
    const int tj_tab[10] = {0, 1, 2, 3, 1, 2, 3, 2, 3, 3};
    const int ti = ti_tab[wid];
    const int tj = tj_tab[wid];

    float acc[2][4][4];
#pragma unroll
    for (int mt = 0; mt < 2; ++mt)
#pragma unroll
        for (int nt = 0; nt < 4; ++nt)
#pragma unroll
            for (int e = 0; e < 4; ++e) acc[mt][nt][e] = 0.0f;

    const uint32_t smem0 = smem_u32(xt);

    // ldmatrix.x4.trans lane offsets (bytes within a stage buffer).
    const int g = lane >> 3;
    const int lr = lane & 7;
    uint32_t aoff[2], boff[2];
#pragma unroll
    for (int mt = 0; mt < 2; ++mt) {
        const int r0 = ti * 32 + mt * 16;
        aoff[mt] = (uint32_t)((lr + ((g >= 2) ? 8 : 0)) * kRowB + r0 * 2 +
                              ((g & 1) ? 16 : 0));
    }
#pragma unroll
    for (int np = 0; np < 2; ++np) {
        const int c0 = tj * 32 + np * 16;
        boff[np] = (uint32_t)((lr + ((g & 1) ? 8 : 0)) * kRowB + c0 * 2 +
                              ((g >= 2) ? 16 : 0));
    }

    // Loader mapping: warp w (0..7) owns smem rows w*4 .. w*4+3 per stage.
    // Lanes 0-15: xr (m 0..63), lanes 16-31: xi (m 64..127); float4 each.
    const bool loader = (wid < 8);
    const int half_sel = lane >> 4;
    const int li = lane & 15;
    const float* src = half_sel ? xi : xr;
    const size_t gbase =
        ((size_t)b * kS + (size_t)(it0 * kBK) + (size_t)(wid * 4)) * kD +
        (size_t)(4 * li);
    const uint32_t sts_off =
        (uint32_t)(wid * 4 * kRowB + half_sel * 128 + li * 8);

    float4 cur[4];
    if (loader) {
        // Stage 0 -> buf 0; prefetch stage 1 into regs.
#pragma unroll
        for (int j = 0; j < 4; ++j) {
            const float4 v =
                *reinterpret_cast<const float4*>(src + gbase + (size_t)j * kD);
            sts_f4h(smem0 + sts_off + (uint32_t)(j * kRowB), v);
        }
        if (niter > 1) {
#pragma unroll
            for (int j = 0; j < 4; ++j)
                cur[j] = *reinterpret_cast<const float4*>(src + gbase +
                                                          (size_t)(32 + j) * kD);
        }
    }

    for (int it = 0; it < niter; ++it) {
        const int s = it & 1;
        __syncthreads();  // buf[s] ready; buf[s^1] free

        if (loader) {
            if (it + 1 < niter) {
                const uint32_t dst = smem0 + (uint32_t)((s ^ 1) * kStageB) + sts_off;
#pragma unroll
                for (int j = 0; j < 4; ++j)
                    sts_f4h(dst + (uint32_t)(j * kRowB), cur[j]);
            }
            if (it + 2 < niter) {
                const size_t goff = gbase + (size_t)((it + 2) * kBK) * kD;
#pragma unroll
                for (int j = 0; j < 4; ++j)
                    cur[j] = *reinterpret_cast<const float4*>(src + goff +
                                                              (size_t)j * kD);
            }
        }

        const uint32_t sb = smem0 + (uint32_t)(s * kStageB);
#pragma unroll
        for (int ks = 0; ks < 2; ++ks) {
            const uint32_t ko = (uint32_t)(ks * 16 * kRowB);
            uint32_t A0[4], A1[4], B0[4], B1[4];
            ldsm_x4_t(sb + ko + aoff[0], A0);
            ldsm_x4_t(sb + ko + aoff[1], A1);
            ldsm_x4_t(sb + ko + boff[0], B0);
            ldsm_x4_t(sb + ko + boff[1], B1);
            mma_f16(acc[0][0], A0, B0 + 0, B0 + 1);
            mma_f16(acc[0][1], A0, B0 + 2, B0 + 3);
            mma_f16(acc[0][2], A0, B1 + 0, B1 + 1);
            mma_f16(acc[0][3], A0, B1 + 2, B1 + 3);
            mma_f16(acc[1][0], A1, B0 + 0, B0 + 1);
            mma_f16(acc[1][1], A1, B0 + 2, B0 + 3);
            mma_f16(acc[1][2], A1, B1 + 0, B1 + 1);
            mma_f16(acc[1][3], A1, B1 + 2, B1 + 3);
        }
    }

    // Epilogue: write this warp's 32x32 tile to scratch (float2 stores).
    const int fr = lane >> 2;
    const int fc = lane & 3;
    float* scr = g_scratch + (size_t)(b * kSplit + p) * kM * kM;
#pragma unroll
    for (int mt = 0; mt < 2; ++mt) {
#pragma unroll
        for (int nt = 0; nt < 4; ++nt) {
            const int row = ti * 32 + mt * 16 + fr;
            const int col = tj * 32 + nt * 8 + 2 * fc;
            float2 v0 = make_float2(acc[mt][nt][0], acc[mt][nt][1]);
            float2 v1 = make_float2(acc[mt][nt][2], acc[mt][nt][3]);
            *reinterpret_cast<float2*>(scr + (size_t)row * kM + col) = v0;
            *reinterpret_cast<float2*>(scr + (size_t)(row + 8) * kM + col) = v1;
        }
    }
}

// ---------------------------------------------------------------------------
// Kernel 2: fused epilogue. grid = 128: (batch, quarter q).
//   q=0: real rows  0..31  tiles (0,0),(0,1),(2,2),(2,3)
//   q=1: real rows 32..63  tiles (0,1),(1,1),(2,3),(3,3)
//   q=2: imag rows  0..31  tiles (0,2),(0,3),(1,2)
//   q=3: imag rows 32..63  tiles (1,2),(1,3),(0,3)
// Tiles are split-summed into padded smem; outputs computed with smem
// transposes (pitch 33, conflict-free) and float4-coalesced GMEM writes.
// ---------------------------------------------------------------------------
__global__ void __launch_bounds__(512)
epilogue_kernel(float* __restrict__ out) {
    __shared__ float tl[4][32][33];

    const int b = blockIdx.x >> 2;
    const int q = blockIdx.x & 3;
    const int t = threadIdx.x;
    const float invS = 1.0f / (float)kS;

    const int ti_all[4][4] = {{0, 0, 2, 2}, {0, 1, 2, 3},
                              {0, 0, 1, 1}, {1, 1, 0, 0}};
    const int tj_all[4][4] = {{0, 1, 2, 3}, {1, 1, 3, 3},
                              {2, 3, 2, 2}, {2, 3, 3, 3}};
    const int ntiles = (q < 2) ? 4 : 3;

    // Stage the needed tiles, summed over the kSplit partials (5+4 chains).
    const float* base = g_scratch + (size_t)b * kSplit * kM * kM;
    for (int idx = t; idx < ntiles * 256; idx += 512) {
        const int slot = idx >> 8;
        const int e = idx & 255;
        const int r = e >> 3;
        const int c4 = (e & 7) * 4;
        const float* src = base +
            (size_t)(ti_all[q][slot] * 32 + r) * kM +
            (size_t)(tj_all[q][slot] * 32 + c4);
        float4 s0 = make_float4(0.f, 0.f, 0.f, 0.f);
        float4 s1 = make_float4(0.f, 0.f, 0.f, 0.f);
#pragma unroll
        for (int pp = 0; pp < 5; ++pp) {
            const float4 v =
                *reinterpret_cast<const float4*>(src + (size_t)pp * kM * kM);
            s0.x += v.x; s0.y += v.y; s0.z += v.z; s0.w += v.w;
        }
#pragma unroll
        for (int pp = 5; pp < kSplit; ++pp) {
            const float4 v =
                *reinterpret_cast<const float4*>(src + (size_t)pp * kM * kM);
            s1.x += v.x; s1.y += v.y; s1.z += v.z; s1.w += v.w;
        }
        tl[slot][r][c4 + 0] = s0.x + s1.x;
        tl[slot][r][c4 + 1] = s0.y + s1.y;
        tl[slot][r][c4 + 2] = s0.z + s1.z;
        tl[slot][r][c4 + 3] = s0.w + s1.w;
    }
    __syncthreads();

    // Compute 32 rows x 64 cols = 2048 outputs; thread -> 4 consecutive j.
    const int il = t >> 4;            // local row 0..31
    const int j0 = (t & 15) * 4;      // col base
    const int i = (q & 1) * 32 + il;  // global row
    float res[4];
#pragma unroll
    for (int v = 0; v < 4; ++v) {
        const int j = j0 + v;
        float val;
        if (q == 0) {  // real, i<32
            const int ii = (i <= j) ? i : j;
            const int jj = (i <= j) ? j : i;
            val = (jj < 32) ? (tl[0][ii][jj] + tl[2][ii][jj])
                            : (tl[1][ii][jj - 32] + tl[3][ii][jj - 32]);
        } else if (q == 1) {  // real, i>=32
            if (j < 32) {
                val = tl[0][j][il] + tl[2][j][il];
            } else {
                const int jl = j - 32;
                const int ii = (il <= jl) ? il : jl;
                const int jj = (il <= jl) ? jl : il;
                val = tl[1][ii][jj] + tl[3][ii][jj];
            }
        } else if (q == 2) {  // imag, i<32: a=G01[i][j], c=G01[j][i]
            const float a = (j < 32) ? tl[0][i][j] : tl[1][i][j - 32];
            const float c = (j < 32) ? tl[0][j][i] : tl[2][j - 32][i];
            val = a - c;
        } else {  // imag, i>=32
            const float a = (j < 32) ? tl[0][il][j] : tl[1][il][j - 32];
            const float c = (j < 32) ? tl[2][j][il] : tl[1][j - 32][il];
            val = a - c;
        }
        res[v] = val * invS;
    }
    float* dst = out + ((q < 2) ? 0 : (size_t)kB * kD * kD) +
                 (size_t)b * kD * kD + (size_t)i * kD + j0;
    *reinterpret_cast<float4*>(dst) = make_float4(res[0], res[1], res[2], res[3]);
}

// ---------------------------------------------------------------------------
extern "C" void kernel_launch(void* const* d_in, const int* in_sizes, int n_in,
                              void* d_out, int out_size) {
    const float* xr = (const float*)d_in[0];
    const float* xi = (const float*)d_in[1];
    float* out = (float*)d_out;

    gram_kernel<<<kB * kSplit, 320>>>(xr, xi);
    epilogue_kernel<<<kB * 4, 512>>>(out);
}